// round 7
// baseline (speedup 1.0000x reference)
#include <cuda_runtime.h>
#include <cuda_bf16.h>
#include <cstdint>
#include <math.h>

#define T 2048
#define HID 1280
#define NH 16
#define HD 80
#define THID (3*HID)

// ---------------- scratch (static device allocations only) ----------------
__device__ float g_qkv[T*THID];
__device__ float g_q[NH*T*HD];
__device__ float g_k[NH*T*HD];
__device__ float g_v[NH*T*HD];
__device__ float g_att[T*HID];

__device__ __nv_bfloat16 g_xh[T*HID],    g_xl[T*HID];
__device__ __nv_bfloat16 g_wqh[THID*HID], g_wql[THID*HID];
__device__ __nv_bfloat16 g_wph[HID*HID],  g_wpl[HID*HID];
__device__ __nv_bfloat16 g_ah[T*HID],    g_al[T*HID];

// ---------------- helpers ----------------
__device__ __forceinline__ uint32_t smem_to_u32(const void* p) {
    uint32_t a;
    asm("{ .reg .u64 tmp; cvta.to.shared.u64 tmp, %1; cvt.u32.u64 %0, tmp; }"
        : "=r"(a) : "l"(p));
    return a;
}
__device__ __forceinline__ void mma_bf16(float* c, const uint32_t* a, const uint32_t* b) {
    asm volatile("mma.sync.aligned.m16n8k16.row.col.f32.bf16.bf16.f32 "
        "{%0,%1,%2,%3}, {%4,%5,%6,%7}, {%8,%9}, {%0,%1,%2,%3};"
        : "+f"(c[0]), "+f"(c[1]), "+f"(c[2]), "+f"(c[3])
        : "r"(a[0]), "r"(a[1]), "r"(a[2]), "r"(a[3]), "r"(b[0]), "r"(b[1]));
}
__device__ __forceinline__ void ldsm_x4(uint32_t* r, uint32_t addr) {
    asm volatile("ldmatrix.sync.aligned.m8n8.x4.shared.b16 {%0,%1,%2,%3}, [%4];"
        : "=r"(r[0]), "=r"(r[1]), "=r"(r[2]), "=r"(r[3]) : "r"(addr));
}
__device__ __forceinline__ void cp_async16(uint32_t dst, const void* src) {
    asm volatile("cp.async.cg.shared.global [%0], [%1], 16;" :: "r"(dst), "l"(src));
}
#define CP_COMMIT() asm volatile("cp.async.commit_group;" ::: "memory")
#define CP_WAIT1()  asm volatile("cp.async.wait_group 1;" ::: "memory")

// ---------------------------------------------------------------------------
// fp32 -> bf16 hi + bf16 lo split
// ---------------------------------------------------------------------------
__global__ void convert_split_kernel(const float* __restrict__ src,
                                     __nv_bfloat16* __restrict__ h,
                                     __nv_bfloat16* __restrict__ l, int n)
{
    int i = blockIdx.x * blockDim.x + threadIdx.x;
    if (i >= n) return;
    float v = src[i];
    __nv_bfloat16 hh = __float2bfloat16_rn(v);
    h[i] = hh;
    l[i] = __float2bfloat16_rn(v - __bfloat162float(hh));
}

__global__ void convert_splitT_kernel(const float* __restrict__ src,
                                      __nv_bfloat16* __restrict__ h,
                                      __nv_bfloat16* __restrict__ l,
                                      int K, int N)
{
    __shared__ float t[32][33];
    int nb = blockIdx.x * 32, kb = blockIdx.y * 32;
    int tx = threadIdx.x, ty = threadIdx.y;
    #pragma unroll
    for (int j = 0; j < 4; j++)
        t[ty + j * 8][tx] = src[(size_t)(kb + ty + j * 8) * N + nb + tx];
    __syncthreads();
    #pragma unroll
    for (int j = 0; j < 4; j++) {
        float v = t[tx][ty + j * 8];
        __nv_bfloat16 hh = __float2bfloat16_rn(v);
        size_t o = (size_t)(nb + ty + j * 8) * K + kb + tx;
        h[o] = hh;
        l[o] = __float2bfloat16_rn(v - __bfloat162float(hh));
    }
}

// ---------------------------------------------------------------------------
// Split-bf16 tensor-core GEMM via mma.sync.
// Round 7 change: term-major MMA ordering — each accumulator is touched once
// per term with 3 other independent MMAs in between (breaks the back-to-back
// dependent HMMA chains that held tensor pipe at 48%).
// ---------------------------------------------------------------------------
#define BM 128
#define BN 128
#define BK 32
#define ASTRIDE 40
#define TILE_B (128*ASTRIDE*2)
#define STAGE_B (4*TILE_B)
#define GEMM_SMEM (2*STAGE_B)

__global__ __launch_bounds__(256, 2)
void gemm_bf16split_kernel(const __nv_bfloat16* __restrict__ Ah,
                           const __nv_bfloat16* __restrict__ Al,
                           const __nv_bfloat16* __restrict__ Bh,
                           const __nv_bfloat16* __restrict__ Bl,
                           const float* __restrict__ bias,
                           float* __restrict__ C,
                           int M, int N, int K)
{
    extern __shared__ char sm[];
    const uint32_t sbase = smem_to_u32(sm);

    const int tid  = threadIdx.x;
    const int wid  = tid >> 5;
    const int lane = tid & 31;
    const int m0 = blockIdx.y * BM, n0 = blockIdx.x * BN;
    const int wm = (wid >> 1) * 32;
    const int wn = (wid & 1) * 64;

    float acc[2][8][4];
    #pragma unroll
    for (int a = 0; a < 2; a++)
        #pragma unroll
        for (int b = 0; b < 8; b++)
            #pragma unroll
            for (int c = 0; c < 4; c++) acc[a][b][c] = 0.f;

    const int c_row = tid >> 2;
    const int c_col = (tid & 3) * 8;
    const uint32_t s_off  = (uint32_t)(c_row * ASTRIDE + c_col) * 2;
    const uint32_t s_off2 = s_off + 64 * ASTRIDE * 2;

    const __nv_bfloat16* gAh = Ah + (size_t)(m0 + c_row) * K + c_col;
    const __nv_bfloat16* gAl = Al + (size_t)(m0 + c_row) * K + c_col;
    const __nv_bfloat16* gBh = Bh + (size_t)(n0 + c_row) * K + c_col;
    const __nv_bfloat16* gBl = Bl + (size_t)(n0 + c_row) * K + c_col;
    const size_t g2 = (size_t)64 * K;

    const int niter = K / BK;

    {
        uint32_t sb = sbase;
        cp_async16(sb + s_off,             gAh);
        cp_async16(sb + s_off2,            gAh + g2);
        cp_async16(sb + TILE_B + s_off,    gAl);
        cp_async16(sb + TILE_B + s_off2,   gAl + g2);
        cp_async16(sb + 2*TILE_B + s_off,  gBh);
        cp_async16(sb + 2*TILE_B + s_off2, gBh + g2);
        cp_async16(sb + 3*TILE_B + s_off,  gBl);
        cp_async16(sb + 3*TILE_B + s_off2, gBl + g2);
    }
    CP_COMMIT();

    const int a_row = (lane & 15);
    const int a_colb = ((lane >> 4) << 3) * 2;
    const int b_row = (lane & 7) + ((lane >> 4) << 3);
    const int b_colb = (((lane >> 3) & 1) << 3) * 2;

    for (int it = 0; it < niter; it++) {
        int nk = it + 1;
        if (nk < niter) {
            uint32_t sb = sbase + (nk & 1) * STAGE_B;
            int k0 = nk * BK;
            cp_async16(sb + s_off,             gAh + k0);
            cp_async16(sb + s_off2,            gAh + g2 + k0);
            cp_async16(sb + TILE_B + s_off,    gAl + k0);
            cp_async16(sb + TILE_B + s_off2,   gAl + g2 + k0);
            cp_async16(sb + 2*TILE_B + s_off,  gBh + k0);
            cp_async16(sb + 2*TILE_B + s_off2, gBh + g2 + k0);
            cp_async16(sb + 3*TILE_B + s_off,  gBl + k0);
            cp_async16(sb + 3*TILE_B + s_off2, gBl + g2 + k0);
        }
        CP_COMMIT();
        CP_WAIT1();
        __syncthreads();

        const uint32_t sb = sbase + (it & 1) * STAGE_B;
        const uint32_t sAh = sb;
        const uint32_t sAl = sb + TILE_B;
        const uint32_t sBh = sb + 2*TILE_B;
        const uint32_t sBl = sb + 3*TILE_B;

        #pragma unroll
        for (int k16 = 0; k16 < 2; k16++) {
            const int kcb = k16 * 32;
            uint32_t ah[2][4], al[2][4];
            #pragma unroll
            for (int mi = 0; mi < 2; mi++) {
                uint32_t ro = (uint32_t)(wm + mi*16 + a_row) * (ASTRIDE*2) + kcb + a_colb;
                ldsm_x4(ah[mi], sAh + ro);
                ldsm_x4(al[mi], sAl + ro);
            }
            #pragma unroll
            for (int g = 0; g < 4; g++) {
                uint32_t ro = (uint32_t)(wn + g*16 + b_row) * (ASTRIDE*2) + kcb + b_colb;
                uint32_t bh[4], bl[4];
                ldsm_x4(bh, sBh + ro);
                ldsm_x4(bl, sBl + ro);
                // term-major: 4 independent MMAs per term, each acc touched
                // once per term -> dependency distance 4 instead of 1.
                #pragma unroll
                for (int mi = 0; mi < 2; mi++) {
                    mma_bf16(acc[mi][g*2+0], ah[mi], bh + 0);
                    mma_bf16(acc[mi][g*2+1], ah[mi], bh + 2);
                }
                #pragma unroll
                for (int mi = 0; mi < 2; mi++) {
                    mma_bf16(acc[mi][g*2+0], ah[mi], bl + 0);
                    mma_bf16(acc[mi][g*2+1], ah[mi], bl + 2);
                }
                #pragma unroll
                for (int mi = 0; mi < 2; mi++) {
                    mma_bf16(acc[mi][g*2+0], al[mi], bh + 0);
                    mma_bf16(acc[mi][g*2+1], al[mi], bh + 2);
                }
            }
        }
        __syncthreads();
    }

    #pragma unroll
    for (int mi = 0; mi < 2; mi++) {
        int r0 = m0 + wm + mi*16 + (lane >> 2);
        #pragma unroll
        for (int t = 0; t < 8; t++) {
            int col = n0 + wn + t*8 + (lane & 3)*2;
            float b0 = bias[col], b1 = bias[col + 1];
            float2 v0 = { acc[mi][t][0] + b0, acc[mi][t][1] + b1 };
            float2 v1 = { acc[mi][t][2] + b0, acc[mi][t][3] + b1 };
            *(float2*)(C + (size_t)r0 * N + col)       = v0;
            *(float2*)(C + (size_t)(r0 + 8) * N + col) = v1;
        }
    }
}

// ---------------------------------------------------------------------------
// RoPE + split qkv into per-head [head][T][80] buffers.
// ---------------------------------------------------------------------------
__global__ void rope_split_kernel(const float* __restrict__ rope)
{
    int idx = blockIdx.x * blockDim.x + threadIdx.x;
    if (idx >= T * NH * HD) return;
    int d = idx % HD;
    int n = (idx / HD) % NH;
    int t = idx / (HD * NH);

    int dr = (d < 40) ? d : d - 40;
    float ang = rope[t * 40 + dr];
    float c = cosf(ang), s = sinf(ang);

    const float* qrow = g_qkv + (size_t)t * THID + n * HD;
    float qv, kv;
    if (d < 40) {
        qv = qrow[d] * c        - qrow[d + 40] * s;
        kv = qrow[HID + d] * c  - qrow[HID + d + 40] * s;
    } else {
        qv = qrow[d - 40] * s       + qrow[d] * c;
        kv = qrow[HID + d - 40] * s + qrow[HID + d] * c;
    }
    int o = (n * T + t) * HD + d;
    g_q[o] = qv;
    g_k[o] = kv;
    g_v[o] = qrow[2 * HID + d];
}

// ---------------------------------------------------------------------------
// Flash attention, block-diagonal masking. Round 7 change:
// chunked online softmax — only 8 scores live at a time (sc[8] instead of
// sc[32]) to kill register spills / occupancy collapse. Since every lane
// holds fully-reduced scores, chunk max needs no shuffles.
// ---------------------------------------------------------------------------
#define AST 84          // padded row stride (floats); 84 = 21 float4
#define AST4 21

__global__ __launch_bounds__(256, 3)
void attn_kernel(const int* __restrict__ seg)
{
    __shared__ float Ks[2 * 32 * AST];
    __shared__ float Vs[2 * 32 * AST];
    __shared__ int   segk[2 * 32];

    const int n = blockIdx.y;
    const int q0 = blockIdx.x * 64;
    const int tid = threadIdx.x;
    const int row = tid >> 2;      // 0..63
    const int sub = tid & 3;       // 0..3

    // Q row chunk in registers (20 floats = 5 float4)
    float4 q4[5];
    {
        const float4* qsrc = (const float4*)(g_q + (size_t)(n * T + q0 + row) * HD + sub * 20);
        #pragma unroll
        for (int i = 0; i < 5; i++) q4[i] = qsrc[i];
    }

    const int myseg  = seg[q0 + row];
    const int seg_lo = seg[q0];
    const int seg_hi = seg[q0 + 63];

    int lo = 0, hi = T;
    while (lo < hi) { int mid = (lo + hi) >> 1; if (seg[mid] < seg_lo) lo = mid + 1; else hi = mid; }
    const int kstart = lo;
    hi = T;
    while (lo < hi) { int mid = (lo + hi) >> 1; if (seg[mid] <= seg_hi) lo = mid + 1; else hi = mid; }
    const int kend = lo;

    const int kb0 = kstart & ~31;
    const int n_tiles = (kend - kb0 + 31) >> 5;

    // prefetch tile 0 into buffer 0
    {
        const int kb = kb0;
        float4* Kd = (float4*)Ks;
        float4* Vd = (float4*)Vs;
        for (int i = tid; i < 32 * 20; i += 256) {
            int kk = i / 20, d4 = i % 20;
            int kg = kb + kk;
            float4 kv = {0.f,0.f,0.f,0.f}, vv = {0.f,0.f,0.f,0.f};
            if (kg < kend) {
                const float4* kr = (const float4*)(g_k + (size_t)(n * T + kg) * HD);
                const float4* vr = (const float4*)(g_v + (size_t)(n * T + kg) * HD);
                kv = kr[d4]; vv = vr[d4];
            }
            Kd[kk * AST4 + d4] = kv;
            Vd[kk * AST4 + d4] = vv;
        }
        if (tid < 32) segk[tid] = (kb + tid < T) ? seg[kb + tid] : -1;
    }
    __syncthreads();

    float m = -1e30f, l = 0.f;
    float accv[20];
    #pragma unroll
    for (int i = 0; i < 20; i++) accv[i] = 0.f;
    const float scale = 0.11180339887498949f;   // 1/sqrt(80)

    for (int t = 0; t < n_tiles; t++) {
        const int buf = t & 1;
        const int kb = kb0 + t * 32;

        // prefetch next tile into the other buffer
        if (t + 1 < n_tiles) {
            const int kb2 = kb + 32;
            float4* Kd = (float4*)(Ks + ((t + 1) & 1) * 32 * AST);
            float4* Vd = (float4*)(Vs + ((t + 1) & 1) * 32 * AST);
            for (int i = tid; i < 32 * 20; i += 256) {
                int kk = i / 20, d4 = i % 20;
                int kg = kb2 + kk;
                float4 kv = {0.f,0.f,0.f,0.f}, vv = {0.f,0.f,0.f,0.f};
                if (kg < kend) {
                    const float4* kr = (const float4*)(g_k + (size_t)(n * T + kg) * HD);
                    const float4* vr = (const float4*)(g_v + (size_t)(n * T + kg) * HD);
                    kv = kr[d4]; vv = vr[d4];
                }
                Kd[kk * AST4 + d4] = kv;
                Vd[kk * AST4 + d4] = vv;
            }
            if (tid < 32) segk[((t + 1) & 1) * 32 + tid] = (kb2 + tid < T) ? seg[kb2 + tid] : -1;
        }

        const float4* Kb4 = (const float4*)(Ks + buf * 32 * AST);
        const float4* Vb4 = (const float4*)(Vs + buf * 32 * AST);
        const int*    sg  = segk + buf * 32;

        // 4 chunks of 8 keys: bounded register pressure.
        #pragma unroll
        for (int c = 0; c < 4; c++) {
            float sc[8];
            #pragma unroll
            for (int j = 0; j < 8; j++) {
                int kk = c * 8 + j;
                const float4* kr = Kb4 + kk * AST4 + sub * 5;
                float s = 0.f;
                #pragma unroll
                for (int i = 0; i < 5; i++) {
                    float4 a = q4[i], b = kr[i];
                    s += a.x * b.x + a.y * b.y + a.z * b.z + a.w * b.w;
                }
                s += __shfl_xor_sync(0xffffffffu, s, 1);
                s += __shfl_xor_sync(0xffffffffu, s, 2);
                sc[j] = s * scale;
            }

            unsigned vb = 0;
            float cm = -1e30f;
            #pragma unroll
            for (int j = 0; j < 8; j++) {
                int kg = kb + c * 8 + j;
                bool ok = (kg >= kstart) && (kg < kend) && (sg[c * 8 + j] == myseg);
                if (ok) { vb |= (1u << j); cm = fmaxf(cm, sc[j]); }
            }

            float mnew = fmaxf(m, cm);
            float factor = __expf(m - mnew);
            m = mnew;
            l *= factor;
            #pragma unroll
            for (int i = 0; i < 20; i++) accv[i] *= factor;

            #pragma unroll
            for (int j = 0; j < 8; j++) {
                float p = (vb & (1u << j)) ? __expf(sc[j] - m) : 0.f;
                l += p;
                const float4* vr = Vb4 + (c * 8 + j) * AST4 + sub * 5;
                #pragma unroll
                for (int i = 0; i < 5; i++) {
                    float4 v = vr[i];
                    accv[i*4+0] += p * v.x;
                    accv[i*4+1] += p * v.y;
                    accv[i*4+2] += p * v.z;
                    accv[i*4+3] += p * v.w;
                }
            }
        }
        __syncthreads();
    }

    float inv = 1.f / l;
    float4* o = (float4*)(g_att + (size_t)(q0 + row) * HID + n * HD + sub * 20);
    #pragma unroll
    for (int i = 0; i < 5; i++) {
        float4 v = { accv[i*4+0]*inv, accv[i*4+1]*inv, accv[i*4+2]*inv, accv[i*4+3]*inv };
        o[i] = v;
    }
}

// ---------------------------------------------------------------------------
extern "C" void kernel_launch(void* const* d_in, const int* in_sizes, int n_in,
                              void* d_out, int out_size)
{
    const float* x     = (const float*)d_in[0];
    const float* rope  = (const float*)d_in[1];
    const int*   seg   = (const int*)  d_in[2];
    const float* qkvW  = (const float*)d_in[3];
    const float* qkvB  = (const float*)d_in[4];
    const float* projW = (const float*)d_in[5];
    const float* projB = (const float*)d_in[6];
    float* out = (float*)d_out;

    float *p_qkv, *p_att;
    cudaGetSymbolAddress((void**)&p_qkv, g_qkv);
    cudaGetSymbolAddress((void**)&p_att, g_att);
    __nv_bfloat16 *p_xh, *p_xl, *p_wqh, *p_wql, *p_wph, *p_wpl, *p_ah, *p_al;
    cudaGetSymbolAddress((void**)&p_xh, g_xh);   cudaGetSymbolAddress((void**)&p_xl, g_xl);
    cudaGetSymbolAddress((void**)&p_wqh, g_wqh); cudaGetSymbolAddress((void**)&p_wql, g_wql);
    cudaGetSymbolAddress((void**)&p_wph, g_wph); cudaGetSymbolAddress((void**)&p_wpl, g_wpl);
    cudaGetSymbolAddress((void**)&p_ah, g_ah);   cudaGetSymbolAddress((void**)&p_al, g_al);

    cudaFuncSetAttribute(gemm_bf16split_kernel,
                         cudaFuncAttributeMaxDynamicSharedMemorySize, GEMM_SMEM);

    // 0. convert inputs to split-bf16 (weights transposed to [N][K])
    convert_split_kernel<<<(T*HID + 255)/256, 256>>>(x, p_xh, p_xl, T*HID);
    convert_splitT_kernel<<<dim3(THID/32, HID/32), dim3(32, 8)>>>(qkvW, p_wqh, p_wql, HID, THID);
    convert_splitT_kernel<<<dim3(HID/32, HID/32), dim3(32, 8)>>>(projW, p_wph, p_wpl, HID, HID);

    // 1. qkv = x @ Wqkv + b   (mma.sync split-bf16)
    gemm_bf16split_kernel<<<dim3(THID/BN, T/BM), 256, GEMM_SMEM>>>(
        p_xh, p_xl, p_wqh, p_wql, qkvB, p_qkv, T, THID, HID);

    // 2. RoPE + split into per-head Q,K,V
    rope_split_kernel<<<(T*NH*HD + 255)/256, 256>>>(rope);

    // 3. Block-diagonal flash attention
    attn_kernel<<<dim3(T/64, NH), 256>>>(seg);

    // 4. convert attention output, then out = att @ Wproj + b
    convert_split_kernel<<<(T*HID + 255)/256, 256>>>(p_att, p_ah, p_al, T*HID);
    gemm_bf16split_kernel<<<dim3(HID/BN, T/BM), 256, GEMM_SMEM>>>(
        p_ah, p_al, p_wph, p_wpl, projB, out, T, HID, HID);
}

// round 8
// speedup vs baseline: 1.6359x; 1.6359x over previous
#include <cuda_runtime.h>
#include <cuda_bf16.h>
#include <cstdint>
#include <math.h>

#define T 2048
#define HID 1280
#define NH 16
#define HD 80
#define THID (3*HID)

// ---------------- scratch (static device allocations only) ----------------
__device__ float g_qkv[T*THID];

__device__ __nv_bfloat16 g_xh[T*HID],    g_xl[T*HID];
__device__ __nv_bfloat16 g_wqh[THID*HID], g_wql[THID*HID];
__device__ __nv_bfloat16 g_wph[HID*HID],  g_wpl[HID*HID];
__device__ __nv_bfloat16 g_ah[T*HID],    g_al[T*HID];

// bf16 hi/lo roped Q,K and V, per head: [head][T][80]
__device__ __nv_bfloat16 g_qh[NH*T*HD], g_ql[NH*T*HD];
__device__ __nv_bfloat16 g_kh[NH*T*HD], g_kl[NH*T*HD];
__device__ __nv_bfloat16 g_vh[NH*T*HD], g_vl[NH*T*HD];

// ---------------- helpers ----------------
__device__ __forceinline__ uint32_t smem_to_u32(const void* p) {
    uint32_t a;
    asm("{ .reg .u64 tmp; cvta.to.shared.u64 tmp, %1; cvt.u32.u64 %0, tmp; }"
        : "=r"(a) : "l"(p));
    return a;
}
__device__ __forceinline__ void mma_bf16(float* c, const uint32_t* a, const uint32_t* b) {
    asm volatile("mma.sync.aligned.m16n8k16.row.col.f32.bf16.bf16.f32 "
        "{%0,%1,%2,%3}, {%4,%5,%6,%7}, {%8,%9}, {%0,%1,%2,%3};"
        : "+f"(c[0]), "+f"(c[1]), "+f"(c[2]), "+f"(c[3])
        : "r"(a[0]), "r"(a[1]), "r"(a[2]), "r"(a[3]), "r"(b[0]), "r"(b[1]));
}
__device__ __forceinline__ void ldsm_x4(uint32_t* r, uint32_t addr) {
    asm volatile("ldmatrix.sync.aligned.m8n8.x4.shared.b16 {%0,%1,%2,%3}, [%4];"
        : "=r"(r[0]), "=r"(r[1]), "=r"(r[2]), "=r"(r[3]) : "r"(addr));
}
__device__ __forceinline__ void ldsm_x4_t(uint32_t* r, uint32_t addr) {
    asm volatile("ldmatrix.sync.aligned.m8n8.x4.trans.shared.b16 {%0,%1,%2,%3}, [%4];"
        : "=r"(r[0]), "=r"(r[1]), "=r"(r[2]), "=r"(r[3]) : "r"(addr));
}
__device__ __forceinline__ void cp_async16(uint32_t dst, const void* src) {
    asm volatile("cp.async.cg.shared.global [%0], [%1], 16;" :: "r"(dst), "l"(src));
}
#define CP_COMMIT() asm volatile("cp.async.commit_group;" ::: "memory")
#define CP_WAIT1()  asm volatile("cp.async.wait_group 1;" ::: "memory")
// pack two fp32 -> bf16x2 register {lo, hi}
__device__ __forceinline__ uint32_t packbf(float lo_, float hi_) {
    uint32_t r;
    asm("cvt.rn.bf16x2.f32 %0, %1, %2;" : "=r"(r) : "f"(hi_), "f"(lo_));
    return r;
}

// ---------------------------------------------------------------------------
// fp32 -> bf16 hi + lo split (x input)
// ---------------------------------------------------------------------------
__global__ void convert_split_kernel(const float* __restrict__ src,
                                     __nv_bfloat16* __restrict__ h,
                                     __nv_bfloat16* __restrict__ l, int n)
{
    int i = blockIdx.x * blockDim.x + threadIdx.x;
    if (i >= n) return;
    float v = src[i];
    __nv_bfloat16 hh = __float2bfloat16_rn(v);
    h[i] = hh;
    l[i] = __float2bfloat16_rn(v - __bfloat162float(hh));
}

__global__ void convert_splitT_kernel(const float* __restrict__ src,
                                      __nv_bfloat16* __restrict__ h,
                                      __nv_bfloat16* __restrict__ l,
                                      int K, int N)
{
    __shared__ float t[32][33];
    int nb = blockIdx.x * 32, kb = blockIdx.y * 32;
    int tx = threadIdx.x, ty = threadIdx.y;
    #pragma unroll
    for (int j = 0; j < 4; j++)
        t[ty + j * 8][tx] = src[(size_t)(kb + ty + j * 8) * N + nb + tx];
    __syncthreads();
    #pragma unroll
    for (int j = 0; j < 4; j++) {
        float v = t[tx][ty + j * 8];
        __nv_bfloat16 hh = __float2bfloat16_rn(v);
        size_t o = (size_t)(nb + ty + j * 8) * K + kb + tx;
        h[o] = hh;
        l[o] = __float2bfloat16_rn(v - __bfloat162float(hh));
    }
}

// ---------------------------------------------------------------------------
// Split-bf16 tensor-core GEMM via mma.sync (unchanged; proven 205us on QKV).
// ---------------------------------------------------------------------------
#define BM 128
#define BN 128
#define BK 32
#define ASTRIDE 40
#define TILE_B (128*ASTRIDE*2)
#define STAGE_B (4*TILE_B)
#define GEMM_SMEM (2*STAGE_B)

__global__ __launch_bounds__(256, 2)
void gemm_bf16split_kernel(const __nv_bfloat16* __restrict__ Ah,
                           const __nv_bfloat16* __restrict__ Al,
                           const __nv_bfloat16* __restrict__ Bh,
                           const __nv_bfloat16* __restrict__ Bl,
                           const float* __restrict__ bias,
                           float* __restrict__ C,
                           int M, int N, int K)
{
    extern __shared__ char sm[];
    const uint32_t sbase = smem_to_u32(sm);

    const int tid  = threadIdx.x;
    const int wid  = tid >> 5;
    const int lane = tid & 31;
    const int m0 = blockIdx.y * BM, n0 = blockIdx.x * BN;
    const int wm = (wid >> 1) * 32;
    const int wn = (wid & 1) * 64;

    float acc[2][8][4];
    #pragma unroll
    for (int a = 0; a < 2; a++)
        #pragma unroll
        for (int b = 0; b < 8; b++)
            #pragma unroll
            for (int c = 0; c < 4; c++) acc[a][b][c] = 0.f;

    const int c_row = tid >> 2;
    const int c_col = (tid & 3) * 8;
    const uint32_t s_off  = (uint32_t)(c_row * ASTRIDE + c_col) * 2;
    const uint32_t s_off2 = s_off + 64 * ASTRIDE * 2;

    const __nv_bfloat16* gAh = Ah + (size_t)(m0 + c_row) * K + c_col;
    const __nv_bfloat16* gAl = Al + (size_t)(m0 + c_row) * K + c_col;
    const __nv_bfloat16* gBh = Bh + (size_t)(n0 + c_row) * K + c_col;
    const __nv_bfloat16* gBl = Bl + (size_t)(n0 + c_row) * K + c_col;
    const size_t g2 = (size_t)64 * K;

    const int niter = K / BK;

    {
        uint32_t sb = sbase;
        cp_async16(sb + s_off,             gAh);
        cp_async16(sb + s_off2,            gAh + g2);
        cp_async16(sb + TILE_B + s_off,    gAl);
        cp_async16(sb + TILE_B + s_off2,   gAl + g2);
        cp_async16(sb + 2*TILE_B + s_off,  gBh);
        cp_async16(sb + 2*TILE_B + s_off2, gBh + g2);
        cp_async16(sb + 3*TILE_B + s_off,  gBl);
        cp_async16(sb + 3*TILE_B + s_off2, gBl + g2);
    }
    CP_COMMIT();

    const int a_row = (lane & 15);
    const int a_colb = ((lane >> 4) << 3) * 2;
    const int b_row = (lane & 7) + ((lane >> 4) << 3);
    const int b_colb = (((lane >> 3) & 1) << 3) * 2;

    for (int it = 0; it < niter; it++) {
        int nk = it + 1;
        if (nk < niter) {
            uint32_t sb = sbase + (nk & 1) * STAGE_B;
            int k0 = nk * BK;
            cp_async16(sb + s_off,             gAh + k0);
            cp_async16(sb + s_off2,            gAh + g2 + k0);
            cp_async16(sb + TILE_B + s_off,    gAl + k0);
            cp_async16(sb + TILE_B + s_off2,   gAl + g2 + k0);
            cp_async16(sb + 2*TILE_B + s_off,  gBh + k0);
            cp_async16(sb + 2*TILE_B + s_off2, gBh + g2 + k0);
            cp_async16(sb + 3*TILE_B + s_off,  gBl + k0);
            cp_async16(sb + 3*TILE_B + s_off2, gBl + g2 + k0);
        }
        CP_COMMIT();
        CP_WAIT1();
        __syncthreads();

        const uint32_t sb = sbase + (it & 1) * STAGE_B;
        const uint32_t sAh = sb;
        const uint32_t sAl = sb + TILE_B;
        const uint32_t sBh = sb + 2*TILE_B;
        const uint32_t sBl = sb + 3*TILE_B;

        #pragma unroll
        for (int k16 = 0; k16 < 2; k16++) {
            const int kcb = k16 * 32;
            uint32_t ah[2][4], al[2][4];
            #pragma unroll
            for (int mi = 0; mi < 2; mi++) {
                uint32_t ro = (uint32_t)(wm + mi*16 + a_row) * (ASTRIDE*2) + kcb + a_colb;
                ldsm_x4(ah[mi], sAh + ro);
                ldsm_x4(al[mi], sAl + ro);
            }
            #pragma unroll
            for (int g = 0; g < 4; g++) {
                uint32_t ro = (uint32_t)(wn + g*16 + b_row) * (ASTRIDE*2) + kcb + b_colb;
                uint32_t bh[4], bl[4];
                ldsm_x4(bh, sBh + ro);
                ldsm_x4(bl, sBl + ro);
                #pragma unroll
                for (int mi = 0; mi < 2; mi++) {
                    mma_bf16(acc[mi][g*2+0], ah[mi], bh + 0);
                    mma_bf16(acc[mi][g*2+1], ah[mi], bh + 2);
                }
                #pragma unroll
                for (int mi = 0; mi < 2; mi++) {
                    mma_bf16(acc[mi][g*2+0], ah[mi], bl + 0);
                    mma_bf16(acc[mi][g*2+1], ah[mi], bl + 2);
                }
                #pragma unroll
                for (int mi = 0; mi < 2; mi++) {
                    mma_bf16(acc[mi][g*2+0], al[mi], bh + 0);
                    mma_bf16(acc[mi][g*2+1], al[mi], bh + 2);
                }
            }
        }
        __syncthreads();
    }

    #pragma unroll
    for (int mi = 0; mi < 2; mi++) {
        int r0 = m0 + wm + mi*16 + (lane >> 2);
        #pragma unroll
        for (int t = 0; t < 8; t++) {
            int col = n0 + wn + t*8 + (lane & 3)*2;
            float b0 = bias[col], b1 = bias[col + 1];
            float2 v0 = { acc[mi][t][0] + b0, acc[mi][t][1] + b1 };
            float2 v1 = { acc[mi][t][2] + b0, acc[mi][t][3] + b1 };
            *(float2*)(C + (size_t)r0 * N + col)       = v0;
            *(float2*)(C + (size_t)(r0 + 8) * N + col) = v1;
        }
    }
}

// ---------------------------------------------------------------------------
// RoPE + split qkv into per-head bf16 hi/lo Q,K,V buffers [head][T][80].
// ---------------------------------------------------------------------------
__global__ void rope_split_kernel(const float* __restrict__ rope)
{
    int idx = blockIdx.x * blockDim.x + threadIdx.x;
    if (idx >= T * NH * HD) return;
    int d = idx % HD;
    int n = (idx / HD) % NH;
    int t = idx / (HD * NH);

    int dr = (d < 40) ? d : d - 40;
    float ang = rope[t * 40 + dr];
    float c = cosf(ang), s = sinf(ang);

    const float* qrow = g_qkv + (size_t)t * THID + n * HD;
    float qv, kv;
    if (d < 40) {
        qv = qrow[d] * c        - qrow[d + 40] * s;
        kv = qrow[HID + d] * c  - qrow[HID + d + 40] * s;
    } else {
        qv = qrow[d - 40] * s       + qrow[d] * c;
        kv = qrow[HID + d - 40] * s + qrow[HID + d] * c;
    }
    float vv = qrow[2 * HID + d];
    int o = (n * T + t) * HD + d;
    __nv_bfloat16 h;
    h = __float2bfloat16_rn(qv); g_qh[o] = h; g_ql[o] = __float2bfloat16_rn(qv - __bfloat162float(h));
    h = __float2bfloat16_rn(kv); g_kh[o] = h; g_kl[o] = __float2bfloat16_rn(kv - __bfloat162float(h));
    h = __float2bfloat16_rn(vv); g_vh[o] = h; g_vl[o] = __float2bfloat16_rn(vv - __bfloat162float(h));
}

// ---------------------------------------------------------------------------
// Tensor-core flash attention with block-diagonal masking.
// CTA: (64 Q rows, 1 head); 4 warps x m16 rows. K-tiles of 32 keys,
// double-buffered smem. Split-bf16 3-term for QK^T and PV; fp32 softmax.
// smem stage: Kh[32][88] Kl Vh Vl (5632B each, 22528B/stage, 2 stages).
// Q (hi/lo [64][88]) transiently uses the stage-1 region during prologue.
// ---------------------------------------------------------------------------
#define KVSB 176            // 88 bf16 row stride, conflict-free for ldmatrix
#define STG  22528

__device__ __forceinline__ void attn_prefetch(char* sm_, int sbuf, int n, int kb,
                                              const int* __restrict__ seg,
                                              int tid, int* segk)
{
    char* dst = sm_ + sbuf * STG;
    #pragma unroll
    for (int i = 0; i < 10; i++) {
        int c = tid + i * 128;             // 0..1279
        int arr = c / 320, w = c % 320;
        int key = w / 10, cb = (w % 10) * 16;
        int kg = kb + key;
        uint4 v = make_uint4(0u, 0u, 0u, 0u);
        const __nv_bfloat16* base = (arr == 0) ? g_kh : (arr == 1) ? g_kl
                                  : (arr == 2) ? g_vh : g_vl;
        if (kg < T)
            v = *(const uint4*)((const char*)(base + (size_t)(n * T + kg) * HD) + cb);
        *(uint4*)(dst + arr * 5632 + key * KVSB + cb) = v;
    }
    if (tid < 32) segk[sbuf * 32 + tid] = (kb + tid < T) ? seg[kb + tid] : -1;
}

__global__ __launch_bounds__(128)
void attn_mma_kernel(const int* __restrict__ seg)
{
    __shared__ __align__(16) char sm_[2 * STG + 256];
    int* segk = (int*)(sm_ + 2 * STG);
    const uint32_t sb0 = smem_to_u32(sm_);

    const int n = blockIdx.y;
    const int q0 = blockIdx.x * 64;
    const int tid = threadIdx.x;
    const int lane = tid & 31;
    const int wid = tid >> 5;
    const int wr = wid * 16;

    const int seg_lo = seg[q0], seg_hi = seg[q0 + 63];
    int lo = 0, hi = T;
    while (lo < hi) { int mid = (lo + hi) >> 1; if (seg[mid] < seg_lo) lo = mid + 1; else hi = mid; }
    const int kstart = lo;
    hi = T;
    while (lo < hi) { int mid = (lo + hi) >> 1; if (seg[mid] <= seg_hi) lo = mid + 1; else hi = mid; }
    const int kend = lo;
    const int kb0 = kstart & ~31;
    const int n_tiles = (kend - kb0 + 31) >> 5;

    const int myseg0 = seg[q0 + wr + (lane >> 2)];
    const int myseg1 = seg[q0 + wr + (lane >> 2) + 8];

    // ---- prologue: Q tile -> smem (stage-1 region), stage-0 KV prefetch
    {
        const char* gq_h = (const char*)(g_qh + (size_t)(n * T + q0) * HD);
        const char* gq_l = (const char*)(g_ql + (size_t)(n * T + q0) * HD);
        #pragma unroll
        for (int i = 0; i < 5; i++) {
            int c = tid + i * 128;            // 0..639
            int row = c / 10, cb = (c % 10) * 16;
            *(uint4*)(sm_ + STG + row * KVSB + cb)         = *(const uint4*)(gq_h + row * 160 + cb);
            *(uint4*)(sm_ + STG + 11264 + row * KVSB + cb) = *(const uint4*)(gq_l + row * 160 + cb);
        }
    }
    attn_prefetch(sm_, 0, n, kb0, seg, tid, segk);
    __syncthreads();

    // Q A-fragments for all 5 k16 steps (hi and lo), kept in registers.
    uint32_t qfh[5][4], qfl[5][4];
    {
        uint32_t base_h = sb0 + STG + (uint32_t)(wr + (lane & 15)) * KVSB + ((lane >> 4) * 8) * 2;
        uint32_t base_l = base_h + 11264;
        #pragma unroll
        for (int ks = 0; ks < 5; ks++) {
            ldsm_x4(qfh[ks], base_h + ks * 32);
            ldsm_x4(qfl[ks], base_l + ks * 32);
        }
    }
    __syncthreads();   // Q region now free for stage-1 prefetch

    float OC[10][4];
    #pragma unroll
    for (int i = 0; i < 10; i++) { OC[i][0] = OC[i][1] = OC[i][2] = OC[i][3] = 0.f; }
    float m0 = -1e30f, m1 = -1e30f, l0 = 0.f, l1 = 0.f;
    const float scale = 0.11180339887498949f;   // 1/sqrt(80)

    for (int t = 0; t < n_tiles; t++) {
        if (t + 1 < n_tiles) attn_prefetch(sm_, (t + 1) & 1, n, kb0 + (t + 1) * 32, seg, tid, segk);
        const uint32_t sb = sb0 + (t & 1) * STG;
        const int* sgk = segk + (t & 1) * 32;
        const int kb = kb0 + t * 32;
        (void)kb;

        // ---- S = Q K^T (3-term split), 4 n8-groups of keys
        float SC[4][4];
        #pragma unroll
        for (int g = 0; g < 4; g++) SC[g][0] = SC[g][1] = SC[g][2] = SC[g][3] = 0.f;

        const int krow = ((lane & 16) >> 1) + (lane & 7);
        #pragma unroll
        for (int ks = 0; ks < 5; ks++) {
            const int dimb = (ks * 16 + ((lane >> 3) & 1) * 8) * 2;
            #pragma unroll
            for (int gp = 0; gp < 2; gp++) {
                uint32_t kh[4], kl[4];
                uint32_t a = sb + (uint32_t)(16 * gp + krow) * KVSB + dimb;
                ldsm_x4(kh, a);            // Kh at stage offset 0
                ldsm_x4(kl, a + 5632);     // Kl
                #pragma unroll
                for (int h = 0; h < 2; h++) {
                    int g = 2 * gp + h;
                    mma_bf16(SC[g], qfh[ks], kh + 2 * h);
                    mma_bf16(SC[g], qfh[ks], kl + 2 * h);
                    mma_bf16(SC[g], qfl[ks], kh + 2 * h);
                }
            }
        }

        // ---- mask + online softmax
        float sM[4][4];
        #pragma unroll
        for (int g = 0; g < 4; g++) {
            int k0i = 8 * g + 2 * (lane & 3);
            int sA = sgk[k0i], sB = sgk[k0i + 1];
            sM[g][0] = (sA == myseg0) ? SC[g][0] * scale : -1e30f;
            sM[g][1] = (sB == myseg0) ? SC[g][1] * scale : -1e30f;
            sM[g][2] = (sA == myseg1) ? SC[g][2] * scale : -1e30f;
            sM[g][3] = (sB == myseg1) ? SC[g][3] * scale : -1e30f;
        }
        float cm0 = -1e30f, cm1 = -1e30f;
        #pragma unroll
        for (int g = 0; g < 4; g++) {
            cm0 = fmaxf(cm0, fmaxf(sM[g][0], sM[g][1]));
            cm1 = fmaxf(cm1, fmaxf(sM[g][2], sM[g][3]));
        }
        cm0 = fmaxf(cm0, __shfl_xor_sync(0xffffffffu, cm0, 1));
        cm0 = fmaxf(cm0, __shfl_xor_sync(0xffffffffu, cm0, 2));
        cm1 = fmaxf(cm1, __shfl_xor_sync(0xffffffffu, cm1, 1));
        cm1 = fmaxf(cm1, __shfl_xor_sync(0xffffffffu, cm1, 2));
        float nm0 = fmaxf(m0, cm0), nm1 = fmaxf(m1, cm1);
        float f0 = __expf(m0 - nm0), f1 = __expf(m1 - nm1);
        m0 = nm0; m1 = nm1;
        l0 *= f0; l1 *= f1;
        #pragma unroll
        for (int i = 0; i < 10; i++) {
            OC[i][0] *= f0; OC[i][1] *= f0; OC[i][2] *= f1; OC[i][3] *= f1;
        }

        float p[4][4];
        #pragma unroll
        for (int g = 0; g < 4; g++) {
            p[g][0] = __expf(sM[g][0] - m0); p[g][1] = __expf(sM[g][1] - m0);
            p[g][2] = __expf(sM[g][2] - m1); p[g][3] = __expf(sM[g][3] - m1);
            l0 += p[g][0] + p[g][1];
            l1 += p[g][2] + p[g][3];
        }

        // ---- pack P -> bf16 hi/lo A-fragments (2 k16 steps over 32 keys)
        uint32_t pah[2][4], pal[2][4];
        #pragma unroll
        for (int ks2 = 0; ks2 < 2; ks2++) {
            #pragma unroll
            for (int pos = 0; pos < 4; pos++) {
                int g = 2 * ks2 + (pos >> 1);
                int e = (pos & 1) * 2;
                float x0 = p[g][e], x1 = p[g][e + 1];
                float h0 = __bfloat162float(__float2bfloat16_rn(x0));
                float h1 = __bfloat162float(__float2bfloat16_rn(x1));
                pah[ks2][pos] = packbf(h0, h1);
                pal[ks2][pos] = packbf(x0 - h0, x1 - h1);
            }
        }

        // ---- O += P V (3-term split), 10 n8-groups of dims
        #pragma unroll
        for (int ks2 = 0; ks2 < 2; ks2++) {
            const int vkey = 16 * ks2 + (lane & 15);
            const int vhalf = ((lane >> 4) & 1) * 16;
            #pragma unroll
            for (int dp = 0; dp < 5; dp++) {
                uint32_t vh[4], vl[4];
                uint32_t a = sb + 11264 + (uint32_t)vkey * KVSB + dp * 32 + vhalf;
                ldsm_x4_t(vh, a);           // Vh at stage offset 11264
                ldsm_x4_t(vl, a + 5632);    // Vl
                mma_bf16(OC[2*dp],     pah[ks2], vh + 0);
                mma_bf16(OC[2*dp],     pah[ks2], vl + 0);
                mma_bf16(OC[2*dp],     pal[ks2], vh + 0);
                mma_bf16(OC[2*dp + 1], pah[ks2], vh + 2);
                mma_bf16(OC[2*dp + 1], pah[ks2], vl + 2);
                mma_bf16(OC[2*dp + 1], pal[ks2], vh + 2);
            }
        }
        __syncthreads();
    }

    // ---- epilogue: normalize, split to bf16 hi/lo att output
    l0 += __shfl_xor_sync(0xffffffffu, l0, 1);
    l0 += __shfl_xor_sync(0xffffffffu, l0, 2);
    l1 += __shfl_xor_sync(0xffffffffu, l1, 1);
    l1 += __shfl_xor_sync(0xffffffffu, l1, 2);
    float inv0 = 1.f / l0, inv1 = 1.f / l1;
    const int row0 = q0 + wr + (lane >> 2);
    const int colb = n * HD + 2 * (lane & 3);
    #pragma unroll
    for (int ng = 0; ng < 10; ng++) {
        int col = colb + 8 * ng;
        float v0 = OC[ng][0] * inv0, v1 = OC[ng][1] * inv0;
        float v2 = OC[ng][2] * inv1, v3 = OC[ng][3] * inv1;
        float h0 = __bfloat162float(__float2bfloat16_rn(v0));
        float h1 = __bfloat162float(__float2bfloat16_rn(v1));
        float h2 = __bfloat162float(__float2bfloat16_rn(v2));
        float h3 = __bfloat162float(__float2bfloat16_rn(v3));
        *(uint32_t*)(g_ah + (size_t)row0 * HID + col)       = packbf(h0, h1);
        *(uint32_t*)(g_al + (size_t)row0 * HID + col)       = packbf(v0 - h0, v1 - h1);
        *(uint32_t*)(g_ah + (size_t)(row0 + 8) * HID + col) = packbf(h2, h3);
        *(uint32_t*)(g_al + (size_t)(row0 + 8) * HID + col) = packbf(v2 - h2, v3 - h3);
    }
}

// ---------------------------------------------------------------------------
extern "C" void kernel_launch(void* const* d_in, const int* in_sizes, int n_in,
                              void* d_out, int out_size)
{
    const float* x     = (const float*)d_in[0];
    const float* rope  = (const float*)d_in[1];
    const int*   seg   = (const int*)  d_in[2];
    const float* qkvW  = (const float*)d_in[3];
    const float* qkvB  = (const float*)d_in[4];
    const float* projW = (const float*)d_in[5];
    const float* projB = (const float*)d_in[6];
    float* out = (float*)d_out;

    float* p_qkv;
    cudaGetSymbolAddress((void**)&p_qkv, g_qkv);
    __nv_bfloat16 *p_xh, *p_xl, *p_wqh, *p_wql, *p_wph, *p_wpl, *p_ah, *p_al;
    cudaGetSymbolAddress((void**)&p_xh, g_xh);   cudaGetSymbolAddress((void**)&p_xl, g_xl);
    cudaGetSymbolAddress((void**)&p_wqh, g_wqh); cudaGetSymbolAddress((void**)&p_wql, g_wql);
    cudaGetSymbolAddress((void**)&p_wph, g_wph); cudaGetSymbolAddress((void**)&p_wpl, g_wpl);
    cudaGetSymbolAddress((void**)&p_ah, g_ah);   cudaGetSymbolAddress((void**)&p_al, g_al);

    cudaFuncSetAttribute(gemm_bf16split_kernel,
                         cudaFuncAttributeMaxDynamicSharedMemorySize, GEMM_SMEM);

    // 0. convert inputs to split-bf16 (weights transposed to [N][K])
    convert_split_kernel<<<(T*HID + 255)/256, 256>>>(x, p_xh, p_xl, T*HID);
    convert_splitT_kernel<<<dim3(THID/32, HID/32), dim3(32, 8)>>>(qkvW, p_wqh, p_wql, HID, THID);
    convert_splitT_kernel<<<dim3(HID/32, HID/32), dim3(32, 8)>>>(projW, p_wph, p_wpl, HID, HID);

    // 1. qkv = x @ Wqkv + b   (mma.sync split-bf16)
    gemm_bf16split_kernel<<<dim3(THID/BN, T/BM), 256, GEMM_SMEM>>>(
        p_xh, p_xl, p_wqh, p_wql, qkvB, p_qkv, T, THID, HID);

    // 2. RoPE + split into per-head bf16 hi/lo Q,K,V
    rope_split_kernel<<<(T*NH*HD + 255)/256, 256>>>(rope);

    // 3. Tensor-core block-diagonal flash attention -> bf16 hi/lo att
    attn_mma_kernel<<<dim3(T/64, NH), 128>>>(seg);

    // 4. out = att @ Wproj + b
    gemm_bf16split_kernel<<<dim3(HID/BN, T/BM), 256, GEMM_SMEM>>>(
        p_ah, p_al, p_wph, p_wpl, projB, out, T, HID, HID);
}

// round 9
// speedup vs baseline: 1.7700x; 1.0820x over previous
#include <cuda_runtime.h>
#include <cuda_bf16.h>
#include <cstdint>
#include <math.h>

#define T 2048
#define HID 1280
#define NH 16
#define HD 80
#define THID (3*HID)

// ---------------- scratch (static device allocations only) ----------------
__device__ float g_qkv[T*THID];

__device__ __nv_bfloat16 g_xh[T*HID],    g_xl[T*HID];
__device__ __nv_bfloat16 g_wqh[THID*HID], g_wql[THID*HID];
__device__ __nv_bfloat16 g_wph[HID*HID],  g_wpl[HID*HID];
__device__ __nv_bfloat16 g_ah[T*HID],    g_al[T*HID];

// bf16 hi/lo roped Q,K and V, per head: [head][T][80]
__device__ __nv_bfloat16 g_qh[NH*T*HD], g_ql[NH*T*HD];
__device__ __nv_bfloat16 g_kh[NH*T*HD], g_kl[NH*T*HD];
__device__ __nv_bfloat16 g_vh[NH*T*HD], g_vl[NH*T*HD];

// ---------------- helpers ----------------
__device__ __forceinline__ uint32_t smem_to_u32(const void* p) {
    uint32_t a;
    asm("{ .reg .u64 tmp; cvta.to.shared.u64 tmp, %1; cvt.u32.u64 %0, tmp; }"
        : "=r"(a) : "l"(p));
    return a;
}
__device__ __forceinline__ void mma_bf16(float* c, const uint32_t* a, const uint32_t* b) {
    asm volatile("mma.sync.aligned.m16n8k16.row.col.f32.bf16.bf16.f32 "
        "{%0,%1,%2,%3}, {%4,%5,%6,%7}, {%8,%9}, {%0,%1,%2,%3};"
        : "+f"(c[0]), "+f"(c[1]), "+f"(c[2]), "+f"(c[3])
        : "r"(a[0]), "r"(a[1]), "r"(a[2]), "r"(a[3]), "r"(b[0]), "r"(b[1]));
}
__device__ __forceinline__ void ldsm_x4(uint32_t* r, uint32_t addr) {
    asm volatile("ldmatrix.sync.aligned.m8n8.x4.shared.b16 {%0,%1,%2,%3}, [%4];"
        : "=r"(r[0]), "=r"(r[1]), "=r"(r[2]), "=r"(r[3]) : "r"(addr));
}
__device__ __forceinline__ void ldsm_x4_t(uint32_t* r, uint32_t addr) {
    asm volatile("ldmatrix.sync.aligned.m8n8.x4.trans.shared.b16 {%0,%1,%2,%3}, [%4];"
        : "=r"(r[0]), "=r"(r[1]), "=r"(r[2]), "=r"(r[3]) : "r"(addr));
}
__device__ __forceinline__ void cp_async16(uint32_t dst, const void* src) {
    asm volatile("cp.async.cg.shared.global [%0], [%1], 16;" :: "r"(dst), "l"(src));
}
#define CP_COMMIT() asm volatile("cp.async.commit_group;" ::: "memory")
#define CP_WAIT1()  asm volatile("cp.async.wait_group 1;" ::: "memory")
__device__ __forceinline__ uint32_t packbf(float lo_, float hi_) {
    uint32_t r;
    asm("cvt.rn.bf16x2.f32 %0, %1, %2;" : "=r"(r) : "f"(hi_), "f"(lo_));
    return r;
}

// ---------------------------------------------------------------------------
// fp32 -> bf16 hi + lo split (x input)
// ---------------------------------------------------------------------------
__global__ void convert_split_kernel(const float* __restrict__ src,
                                     __nv_bfloat16* __restrict__ h,
                                     __nv_bfloat16* __restrict__ l, int n)
{
    int i = blockIdx.x * blockDim.x + threadIdx.x;
    if (i >= n) return;
    float v = src[i];
    __nv_bfloat16 hh = __float2bfloat16_rn(v);
    h[i] = hh;
    l[i] = __float2bfloat16_rn(v - __bfloat162float(hh));
}

__global__ void convert_splitT_kernel(const float* __restrict__ src,
                                      __nv_bfloat16* __restrict__ h,
                                      __nv_bfloat16* __restrict__ l,
                                      int K, int N)
{
    __shared__ float t[32][33];
    int nb = blockIdx.x * 32, kb = blockIdx.y * 32;
    int tx = threadIdx.x, ty = threadIdx.y;
    #pragma unroll
    for (int j = 0; j < 4; j++)
        t[ty + j * 8][tx] = src[(size_t)(kb + ty + j * 8) * N + nb + tx];
    __syncthreads();
    #pragma unroll
    for (int j = 0; j < 4; j++) {
        float v = t[tx][ty + j * 8];
        __nv_bfloat16 hh = __float2bfloat16_rn(v);
        size_t o = (size_t)(nb + ty + j * 8) * K + kb + tx;
        h[o] = hh;
        l[o] = __float2bfloat16_rn(v - __bfloat162float(hh));
    }
}

// ---------------------------------------------------------------------------
// Split-bf16 tensor-core GEMM via mma.sync.
// Round 9: BM 128->64 (warp tile 16x64). smem/stage 30720B, 2 stages ->
// 3 CTAs/SM (24 warps) to cover LDSM latency + barrier skew.
// ---------------------------------------------------------------------------
#define BM 64
#define BN 128
#define BK 32
#define ASTRIDE 40                       // bf16 per smem row (80B)
#define A_TILE (64*80)                   // 5120 B
#define B_TILE (128*80)                  // 10240 B
#define STAGE_B (2*A_TILE + 2*B_TILE)    // 30720 B
#define GEMM_SMEM (2*STAGE_B)            // 61440 B

__global__ __launch_bounds__(256, 3)
void gemm_bf16split_kernel(const __nv_bfloat16* __restrict__ Ah,
                           const __nv_bfloat16* __restrict__ Al,
                           const __nv_bfloat16* __restrict__ Bh,
                           const __nv_bfloat16* __restrict__ Bl,
                           const float* __restrict__ bias,
                           float* __restrict__ C,
                           int M, int N, int K)
{
    extern __shared__ char sm[];
    const uint32_t sbase = smem_to_u32(sm);

    const int tid  = threadIdx.x;
    const int wid  = tid >> 5;
    const int lane = tid & 31;
    const int m0 = blockIdx.y * BM, n0 = blockIdx.x * BN;
    const int wm = (wid >> 1) * 16;       // warp row offset (4 warps x 16 = 64)
    const int wn = (wid & 1) * 64;        // warp col offset

    float acc[8][4];
    #pragma unroll
    for (int b = 0; b < 8; b++)
        #pragma unroll
        for (int c = 0; c < 4; c++) acc[b][c] = 0.f;

    // cp.async mapping: thread -> (row tid>>2, 16B chunk tid&3)
    const int c_row = tid >> 2;            // 0..63
    const int c_col = (tid & 3) * 8;       // bf16 col 0,8,16,24
    const uint32_t s_off  = (uint32_t)(c_row * ASTRIDE + c_col) * 2;
    const uint32_t s_off2 = s_off + (uint32_t)64 * ASTRIDE * 2;

    const __nv_bfloat16* gAh = Ah + (size_t)(m0 + c_row) * K + c_col;
    const __nv_bfloat16* gAl = Al + (size_t)(m0 + c_row) * K + c_col;
    const __nv_bfloat16* gBh = Bh + (size_t)(n0 + c_row) * K + c_col;
    const __nv_bfloat16* gBl = Bl + (size_t)(n0 + c_row) * K + c_col;
    const size_t g2 = (size_t)64 * K;

    const int niter = K / BK;

    {
        uint32_t sb = sbase;
        cp_async16(sb + s_off,                       gAh);
        cp_async16(sb + A_TILE + s_off,              gAl);
        cp_async16(sb + 2*A_TILE + s_off,            gBh);
        cp_async16(sb + 2*A_TILE + s_off2,           gBh + g2);
        cp_async16(sb + 2*A_TILE + B_TILE + s_off,   gBl);
        cp_async16(sb + 2*A_TILE + B_TILE + s_off2,  gBl + g2);
    }
    CP_COMMIT();

    const int a_row  = (lane & 15);
    const int a_colb = (lane >> 4) * 16;               // bytes
    const int b_row  = (lane & 7) + ((lane >> 4) << 3);
    const int b_colb = (((lane >> 3) & 1)) * 16;       // bytes

    for (int it = 0; it < niter; it++) {
        int nk = it + 1;
        if (nk < niter) {
            uint32_t sb = sbase + (nk & 1) * STAGE_B;
            int k0 = nk * BK;
            cp_async16(sb + s_off,                      gAh + k0);
            cp_async16(sb + A_TILE + s_off,             gAl + k0);
            cp_async16(sb + 2*A_TILE + s_off,           gBh + k0);
            cp_async16(sb + 2*A_TILE + s_off2,          gBh + g2 + k0);
            cp_async16(sb + 2*A_TILE + B_TILE + s_off,  gBl + k0);
            cp_async16(sb + 2*A_TILE + B_TILE + s_off2, gBl + g2 + k0);
        }
        CP_COMMIT();
        CP_WAIT1();
        __syncthreads();

        const uint32_t sb  = sbase + (it & 1) * STAGE_B;
        const uint32_t sAh = sb;
        const uint32_t sAl = sb + A_TILE;
        const uint32_t sBh = sb + 2*A_TILE;
        const uint32_t sBl = sb + 2*A_TILE + B_TILE;

        #pragma unroll
        for (int k16 = 0; k16 < 2; k16++) {
            const int kcb = k16 * 32;
            uint32_t ah[4], al[4];
            {
                uint32_t ro = (uint32_t)(wm + a_row) * 80 + kcb + a_colb;
                ldsm_x4(ah, sAh + ro);
                ldsm_x4(al, sAl + ro);
            }
            #pragma unroll
            for (int g = 0; g < 4; g++) {
                uint32_t ro = (uint32_t)(wn + g*16 + b_row) * 80 + kcb + b_colb;
                uint32_t bh[4], bl[4];
                ldsm_x4(bh, sBh + ro);
                ldsm_x4(bl, sBl + ro);
                mma_bf16(acc[g*2+0], ah, bh + 0);
                mma_bf16(acc[g*2+1], ah, bh + 2);
                mma_bf16(acc[g*2+0], ah, bl + 0);
                mma_bf16(acc[g*2+1], ah, bl + 2);
                mma_bf16(acc[g*2+0], al, bh + 0);
                mma_bf16(acc[g*2+1], al, bh + 2);
            }
        }
        __syncthreads();
    }

    // Epilogue: bias add + store
    {
        int r0 = m0 + wm + (lane >> 2);
        #pragma unroll
        for (int t = 0; t < 8; t++) {
            int col = n0 + wn + t*8 + (lane & 3)*2;
            float b0 = bias[col], b1 = bias[col + 1];
            float2 v0 = { acc[t][0] + b0, acc[t][1] + b1 };
            float2 v1 = { acc[t][2] + b0, acc[t][3] + b1 };
            *(float2*)(C + (size_t)r0 * N + col)       = v0;
            *(float2*)(C + (size_t)(r0 + 8) * N + col) = v1;
        }
    }
}

// ---------------------------------------------------------------------------
// RoPE + split qkv into per-head bf16 hi/lo Q,K,V buffers [head][T][80].
// ---------------------------------------------------------------------------
__global__ void rope_split_kernel(const float* __restrict__ rope)
{
    int idx = blockIdx.x * blockDim.x + threadIdx.x;
    if (idx >= T * NH * HD) return;
    int d = idx % HD;
    int n = (idx / HD) % NH;
    int t = idx / (HD * NH);

    int dr = (d < 40) ? d : d - 40;
    float ang = rope[t * 40 + dr];
    float c = cosf(ang), s = sinf(ang);

    const float* qrow = g_qkv + (size_t)t * THID + n * HD;
    float qv, kv;
    if (d < 40) {
        qv = qrow[d] * c        - qrow[d + 40] * s;
        kv = qrow[HID + d] * c  - qrow[HID + d + 40] * s;
    } else {
        qv = qrow[d - 40] * s       + qrow[d] * c;
        kv = qrow[HID + d - 40] * s + qrow[HID + d] * c;
    }
    float vv = qrow[2 * HID + d];
    int o = (n * T + t) * HD + d;
    __nv_bfloat16 h;
    h = __float2bfloat16_rn(qv); g_qh[o] = h; g_ql[o] = __float2bfloat16_rn(qv - __bfloat162float(h));
    h = __float2bfloat16_rn(kv); g_kh[o] = h; g_kl[o] = __float2bfloat16_rn(kv - __bfloat162float(h));
    h = __float2bfloat16_rn(vv); g_vh[o] = h; g_vl[o] = __float2bfloat16_rn(vv - __bfloat162float(h));
}

// ---------------------------------------------------------------------------
// Tensor-core flash attention with block-diagonal masking (proven round 8).
// ---------------------------------------------------------------------------
#define KVSB 176            // 88 bf16 row stride, conflict-free for ldmatrix
#define STG  22528

__device__ __forceinline__ void attn_prefetch(char* sm_, int sbuf, int n, int kb,
                                              const int* __restrict__ seg,
                                              int tid, int* segk)
{
    char* dst = sm_ + sbuf * STG;
    #pragma unroll
    for (int i = 0; i < 10; i++) {
        int c = tid + i * 128;             // 0..1279
        int arr = c / 320, w = c % 320;
        int key = w / 10, cb = (w % 10) * 16;
        int kg = kb + key;
        uint4 v = make_uint4(0u, 0u, 0u, 0u);
        const __nv_bfloat16* base = (arr == 0) ? g_kh : (arr == 1) ? g_kl
                                  : (arr == 2) ? g_vh : g_vl;
        if (kg < T)
            v = *(const uint4*)((const char*)(base + (size_t)(n * T + kg) * HD) + cb);
        *(uint4*)(dst + arr * 5632 + key * KVSB + cb) = v;
    }
    if (tid < 32) segk[sbuf * 32 + tid] = (kb + tid < T) ? seg[kb + tid] : -1;
}

__global__ __launch_bounds__(128)
void attn_mma_kernel(const int* __restrict__ seg)
{
    __shared__ __align__(16) char sm_[2 * STG + 256];
    int* segk = (int*)(sm_ + 2 * STG);
    const uint32_t sb0 = smem_to_u32(sm_);

    const int n = blockIdx.y;
    const int q0 = blockIdx.x * 64;
    const int tid = threadIdx.x;
    const int lane = tid & 31;
    const int wid = tid >> 5;
    const int wr = wid * 16;

    const int seg_lo = seg[q0], seg_hi = seg[q0 + 63];
    int lo = 0, hi = T;
    while (lo < hi) { int mid = (lo + hi) >> 1; if (seg[mid] < seg_lo) lo = mid + 1; else hi = mid; }
    const int kstart = lo;
    hi = T;
    while (lo < hi) { int mid = (lo + hi) >> 1; if (seg[mid] <= seg_hi) lo = mid + 1; else hi = mid; }
    const int kend = lo;
    const int kb0 = kstart & ~31;
    const int n_tiles = (kend - kb0 + 31) >> 5;

    const int myseg0 = seg[q0 + wr + (lane >> 2)];
    const int myseg1 = seg[q0 + wr + (lane >> 2) + 8];

    {
        const char* gq_h = (const char*)(g_qh + (size_t)(n * T + q0) * HD);
        const char* gq_l = (const char*)(g_ql + (size_t)(n * T + q0) * HD);
        #pragma unroll
        for (int i = 0; i < 5; i++) {
            int c = tid + i * 128;            // 0..639
            int row = c / 10, cb = (c % 10) * 16;
            *(uint4*)(sm_ + STG + row * KVSB + cb)         = *(const uint4*)(gq_h + row * 160 + cb);
            *(uint4*)(sm_ + STG + 11264 + row * KVSB + cb) = *(const uint4*)(gq_l + row * 160 + cb);
        }
    }
    attn_prefetch(sm_, 0, n, kb0, seg, tid, segk);
    __syncthreads();

    uint32_t qfh[5][4], qfl[5][4];
    {
        uint32_t base_h = sb0 + STG + (uint32_t)(wr + (lane & 15)) * KVSB + ((lane >> 4) * 8) * 2;
        uint32_t base_l = base_h + 11264;
        #pragma unroll
        for (int ks = 0; ks < 5; ks++) {
            ldsm_x4(qfh[ks], base_h + ks * 32);
            ldsm_x4(qfl[ks], base_l + ks * 32);
        }
    }
    __syncthreads();

    float OC[10][4];
    #pragma unroll
    for (int i = 0; i < 10; i++) { OC[i][0] = OC[i][1] = OC[i][2] = OC[i][3] = 0.f; }
    float m0 = -1e30f, m1 = -1e30f, l0 = 0.f, l1 = 0.f;
    const float scale = 0.11180339887498949f;

    for (int t = 0; t < n_tiles; t++) {
        if (t + 1 < n_tiles) attn_prefetch(sm_, (t + 1) & 1, n, kb0 + (t + 1) * 32, seg, tid, segk);
        const uint32_t sb = sb0 + (t & 1) * STG;
        const int* sgk = segk + (t & 1) * 32;

        float SC[4][4];
        #pragma unroll
        for (int g = 0; g < 4; g++) SC[g][0] = SC[g][1] = SC[g][2] = SC[g][3] = 0.f;

        const int krow = ((lane & 16) >> 1) + (lane & 7);
        #pragma unroll
        for (int ks = 0; ks < 5; ks++) {
            const int dimb = (ks * 16 + ((lane >> 3) & 1) * 8) * 2;
            #pragma unroll
            for (int gp = 0; gp < 2; gp++) {
                uint32_t kh[4], kl[4];
                uint32_t a = sb + (uint32_t)(16 * gp + krow) * KVSB + dimb;
                ldsm_x4(kh, a);
                ldsm_x4(kl, a + 5632);
                #pragma unroll
                for (int h = 0; h < 2; h++) {
                    int g = 2 * gp + h;
                    mma_bf16(SC[g], qfh[ks], kh + 2 * h);
                    mma_bf16(SC[g], qfh[ks], kl + 2 * h);
                    mma_bf16(SC[g], qfl[ks], kh + 2 * h);
                }
            }
        }

        float sM[4][4];
        #pragma unroll
        for (int g = 0; g < 4; g++) {
            int k0i = 8 * g + 2 * (lane & 3);
            int sA = sgk[k0i], sB = sgk[k0i + 1];
            sM[g][0] = (sA == myseg0) ? SC[g][0] * scale : -1e30f;
            sM[g][1] = (sB == myseg0) ? SC[g][1] * scale : -1e30f;
            sM[g][2] = (sA == myseg1) ? SC[g][2] * scale : -1e30f;
            sM[g][3] = (sB == myseg1) ? SC[g][3] * scale : -1e30f;
        }
        float cm0 = -1e30f, cm1 = -1e30f;
        #pragma unroll
        for (int g = 0; g < 4; g++) {
            cm0 = fmaxf(cm0, fmaxf(sM[g][0], sM[g][1]));
            cm1 = fmaxf(cm1, fmaxf(sM[g][2], sM[g][3]));
        }
        cm0 = fmaxf(cm0, __shfl_xor_sync(0xffffffffu, cm0, 1));
        cm0 = fmaxf(cm0, __shfl_xor_sync(0xffffffffu, cm0, 2));
        cm1 = fmaxf(cm1, __shfl_xor_sync(0xffffffffu, cm1, 1));
        cm1 = fmaxf(cm1, __shfl_xor_sync(0xffffffffu, cm1, 2));
        float nm0 = fmaxf(m0, cm0), nm1 = fmaxf(m1, cm1);
        float f0 = __expf(m0 - nm0), f1 = __expf(m1 - nm1);
        m0 = nm0; m1 = nm1;
        l0 *= f0; l1 *= f1;
        #pragma unroll
        for (int i = 0; i < 10; i++) {
            OC[i][0] *= f0; OC[i][1] *= f0; OC[i][2] *= f1; OC[i][3] *= f1;
        }

        float p[4][4];
        #pragma unroll
        for (int g = 0; g < 4; g++) {
            p[g][0] = __expf(sM[g][0] - m0); p[g][1] = __expf(sM[g][1] - m0);
            p[g][2] = __expf(sM[g][2] - m1); p[g][3] = __expf(sM[g][3] - m1);
            l0 += p[g][0] + p[g][1];
            l1 += p[g][2] + p[g][3];
        }

        uint32_t pah[2][4], pal[2][4];
        #pragma unroll
        for (int ks2 = 0; ks2 < 2; ks2++) {
            #pragma unroll
            for (int pos = 0; pos < 4; pos++) {
                int g = 2 * ks2 + (pos >> 1);
                int e = (pos & 1) * 2;
                float x0 = p[g][e], x1 = p[g][e + 1];
                float h0 = __bfloat162float(__float2bfloat16_rn(x0));
                float h1 = __bfloat162float(__float2bfloat16_rn(x1));
                pah[ks2][pos] = packbf(h0, h1);
                pal[ks2][pos] = packbf(x0 - h0, x1 - h1);
            }
        }

        #pragma unroll
        for (int ks2 = 0; ks2 < 2; ks2++) {
            const int vkey = 16 * ks2 + (lane & 15);
            const int vhalf = ((lane >> 4) & 1) * 16;
            #pragma unroll
            for (int dp = 0; dp < 5; dp++) {
                uint32_t vh[4], vl[4];
                uint32_t a = sb + 11264 + (uint32_t)vkey * KVSB + dp * 32 + vhalf;
                ldsm_x4_t(vh, a);
                ldsm_x4_t(vl, a + 5632);
                mma_bf16(OC[2*dp],     pah[ks2], vh + 0);
                mma_bf16(OC[2*dp],     pah[ks2], vl + 0);
                mma_bf16(OC[2*dp],     pal[ks2], vh + 0);
                mma_bf16(OC[2*dp + 1], pah[ks2], vh + 2);
                mma_bf16(OC[2*dp + 1], pah[ks2], vl + 2);
                mma_bf16(OC[2*dp + 1], pal[ks2], vh + 2);
            }
        }
        __syncthreads();
    }

    l0 += __shfl_xor_sync(0xffffffffu, l0, 1);
    l0 += __shfl_xor_sync(0xffffffffu, l0, 2);
    l1 += __shfl_xor_sync(0xffffffffu, l1, 1);
    l1 += __shfl_xor_sync(0xffffffffu, l1, 2);
    float inv0 = 1.f / l0, inv1 = 1.f / l1;
    const int row0 = q0 + wr + (lane >> 2);
    const int colb = n * HD + 2 * (lane & 3);
    #pragma unroll
    for (int ng = 0; ng < 10; ng++) {
        int col = colb + 8 * ng;
        float v0 = OC[ng][0] * inv0, v1 = OC[ng][1] * inv0;
        float v2 = OC[ng][2] * inv1, v3 = OC[ng][3] * inv1;
        float h0 = __bfloat162float(__float2bfloat16_rn(v0));
        float h1 = __bfloat162float(__float2bfloat16_rn(v1));
        float h2 = __bfloat162float(__float2bfloat16_rn(v2));
        float h3 = __bfloat162float(__float2bfloat16_rn(v3));
        *(uint32_t*)(g_ah + (size_t)row0 * HID + col)       = packbf(h0, h1);
        *(uint32_t*)(g_al + (size_t)row0 * HID + col)       = packbf(v0 - h0, v1 - h1);
        *(uint32_t*)(g_ah + (size_t)(row0 + 8) * HID + col) = packbf(h2, h3);
        *(uint32_t*)(g_al + (size_t)(row0 + 8) * HID + col) = packbf(v2 - h2, v3 - h3);
    }
}

// ---------------------------------------------------------------------------
extern "C" void kernel_launch(void* const* d_in, const int* in_sizes, int n_in,
                              void* d_out, int out_size)
{
    const float* x     = (const float*)d_in[0];
    const float* rope  = (const float*)d_in[1];
    const int*   seg   = (const int*)  d_in[2];
    const float* qkvW  = (const float*)d_in[3];
    const float* qkvB  = (const float*)d_in[4];
    const float* projW = (const float*)d_in[5];
    const float* projB = (const float*)d_in[6];
    float* out = (float*)d_out;

    float* p_qkv;
    cudaGetSymbolAddress((void**)&p_qkv, g_qkv);
    __nv_bfloat16 *p_xh, *p_xl, *p_wqh, *p_wql, *p_wph, *p_wpl, *p_ah, *p_al;
    cudaGetSymbolAddress((void**)&p_xh, g_xh);   cudaGetSymbolAddress((void**)&p_xl, g_xl);
    cudaGetSymbolAddress((void**)&p_wqh, g_wqh); cudaGetSymbolAddress((void**)&p_wql, g_wql);
    cudaGetSymbolAddress((void**)&p_wph, g_wph); cudaGetSymbolAddress((void**)&p_wpl, g_wpl);
    cudaGetSymbolAddress((void**)&p_ah, g_ah);   cudaGetSymbolAddress((void**)&p_al, g_al);

    cudaFuncSetAttribute(gemm_bf16split_kernel,
                         cudaFuncAttributeMaxDynamicSharedMemorySize, GEMM_SMEM);

    // 0. convert inputs to split-bf16 (weights transposed to [N][K])
    convert_split_kernel<<<(T*HID + 255)/256, 256>>>(x, p_xh, p_xl, T*HID);
    convert_splitT_kernel<<<dim3(THID/32, HID/32), dim3(32, 8)>>>(qkvW, p_wqh, p_wql, HID, THID);
    convert_splitT_kernel<<<dim3(HID/32, HID/32), dim3(32, 8)>>>(projW, p_wph, p_wpl, HID, HID);

    // 1. qkv = x @ Wqkv + b   (mma.sync split-bf16)
    gemm_bf16split_kernel<<<dim3(THID/BN, T/BM), 256, GEMM_SMEM>>>(
        p_xh, p_xl, p_wqh, p_wql, qkvB, p_qkv, T, THID, HID);

    // 2. RoPE + split into per-head bf16 hi/lo Q,K,V
    rope_split_kernel<<<(T*NH*HD + 255)/256, 256>>>(rope);

    // 3. Tensor-core block-diagonal flash attention -> bf16 hi/lo att
    attn_mma_kernel<<<dim3(T/64, NH), 128>>>(seg);

    // 4. out = att @ Wproj + b
    gemm_bf16split_kernel<<<dim3(HID/BN, T/BM), 256, GEMM_SMEM>>>(
        p_ah, p_al, p_wph, p_wpl, projB, out, T, HID, HID);
}